// round 6
// baseline (speedup 1.0000x reference)
#include <cuda_runtime.h>

// SimpleLSTM: B=4096, T=256, I=16, H=32, O=1 (fp32)
// One-warp blocks (grid 1024) -> balanced 7 warps/SM across all 148 SMs
// (28 batches/SM max instead of 32 on 128 SMs).
// Warp = 4 batches; lane j owns hidden unit j of all 4. W_hh in registers
// (f32x2 pairs, shared by the 4 batches). Gates i,f,o weights pre-scaled by
// 0.5 so sigmoid = fma(tanh(acc),0.5,0.5) with no per-step scaling mul.
// x staged via cp.async double-buffer; h broadcast via smem double-buffer.

#define BB 4096
#define TT 256
#define II 16
#define HH 32
#define BPW 4   // batches per warp

typedef unsigned long long ull;

__device__ __forceinline__ void ffma2(ull& acc, ull a, ull b) {
    asm("fma.rn.f32x2 %0, %1, %2, %0;" : "+l"(acc) : "l"(a), "l"(b));
}
__device__ __forceinline__ float hadd2(ull v) {
    float lo, hi;
    asm("mov.b64 {%0, %1}, %2;" : "=f"(lo), "=f"(hi) : "l"(v));
    return lo + hi;
}
__device__ __forceinline__ ull pack2(float lo, float hi) {
    ull r;
    asm("mov.b64 %0, {%1, %2};" : "=l"(r) : "f"(lo), "f"(hi));
    return r;
}
__device__ __forceinline__ float tanh_a(float v) {
    float r;
    asm("tanh.approx.f32 %0, %1;" : "=f"(r) : "f"(v));   // MUFU.TANH
    return r;
}
__device__ __forceinline__ void cp_async16(void* smem_dst, const void* gsrc) {
    unsigned saddr = (unsigned)__cvta_generic_to_shared(smem_dst);
    asm volatile("cp.async.ca.shared.global [%0], [%1], 16;" :: "r"(saddr), "l"(gsrc));
}
__device__ __forceinline__ void cp_commit() {
    asm volatile("cp.async.commit_group;" ::: "memory");
}
__device__ __forceinline__ void cp_wait1() {
    asm volatile("cp.async.wait_group 1;" ::: "memory");
}

__global__ void __launch_bounds__(32, 7)
lstm_warp4_kernel(const float* __restrict__ x,      // [B,T,I]
                  const float* __restrict__ W_ih,   // [4H,I]
                  const float* __restrict__ W_hh,   // [4H,H]
                  const float* __restrict__ b_ih,   // [4H]
                  const float* __restrict__ b_hh,   // [4H]
                  const float* __restrict__ W_fc,   // [1,H]
                  const float* __restrict__ b_fc,   // [1]
                  float* __restrict__ out)          // [B,1]
{
    // wihA[i2][j] = {0.5*Wi[j][2i2..+1], 0.5*Wf[j][2i2..+1]}
    // wihB[i2][j] = {Wg[j][2i2..+1], 0.5*Wo[j][2i2..+1]}
    __shared__ float4 wihA[II / 2][HH];
    __shared__ float4 wihB[II / 2][HH];
    __shared__ float  h_s[2][BPW][HH];   // h broadcast, double-buffered
    __shared__ float  xs[2][BPW][II];    // x staging, double-buffered

    const int j  = threadIdx.x;          // lane (block = 1 warp)
    const int b0 = blockIdx.x * BPW;

    // gate scale: 0.5 for i,f,o (sigmoid fold), 1.0 for g
    const float gsc[4] = {0.5f, 0.5f, 1.0f, 0.5f};

    // ---- stage W_ih (this warp) ----
    {
        int jj = j;
        #pragma unroll
        for (int i2 = 0; i2 < II / 2; i2++) {
            wihA[i2][jj] = make_float4(0.5f * W_ih[(0 * HH + jj) * II + 2 * i2],
                                       0.5f * W_ih[(0 * HH + jj) * II + 2 * i2 + 1],
                                       0.5f * W_ih[(1 * HH + jj) * II + 2 * i2],
                                       0.5f * W_ih[(1 * HH + jj) * II + 2 * i2 + 1]);
            wihB[i2][jj] = make_float4(W_ih[(2 * HH + jj) * II + 2 * i2],
                                       W_ih[(2 * HH + jj) * II + 2 * i2 + 1],
                                       0.5f * W_ih[(3 * HH + jj) * II + 2 * i2],
                                       0.5f * W_ih[(3 * HH + jj) * II + 2 * i2 + 1]);
        }
    }

    // ---- W_hh rows for this lane's 4 gates as packed pairs (128 regs) ----
    ull whh2[4][HH / 2];
    {
        #pragma unroll
        for (int g = 0; g < 4; g++) {
            const float* wrow = W_hh + (g * HH + j) * HH;
            #pragma unroll
            for (int k2 = 0; k2 < HH / 2; k2++)
                whh2[g][k2] = pack2(gsc[g] * wrow[2 * k2], gsc[g] * wrow[2 * k2 + 1]);
        }
    }

    ull biasp[4];
    #pragma unroll
    for (int g = 0; g < 4; g++)
        biasp[g] = pack2(gsc[g] * (b_ih[g * HH + j] + b_hh[g * HH + j]), 0.0f);

    const ulonglong2* wA = reinterpret_cast<const ulonglong2*>(&wihA[0][j]);
    const ulonglong2* wB = reinterpret_cast<const ulonglong2*>(&wihB[0][j]);

    // cp.async source for this lane (lanes 0..15: batch j>>2, 16B chunk j&3)
    const int cb = j >> 2, cc = j & 3;
    const float* gsrc = x + (long)(b0 + cb) * TT * II + cc * 4;

    float h[BPW] = {0.f, 0.f, 0.f, 0.f};
    float c[BPW] = {0.f, 0.f, 0.f, 0.f};

    // prefetch x(t=0) into buffer 0
    if (j < 16) cp_async16(&xs[0][cb][cc * 4], gsrc);
    cp_commit();
    __syncwarp();

    #pragma unroll 1
    for (int t = 0; t < TT; t++) {
        const int bufx = t & 1;

        // broadcast h (double-buffered)
        #pragma unroll
        for (int bb = 0; bb < BPW; bb++)
            h_s[bufx][bb][j] = h[bb];

        // prefetch next x into other buffer (always commit: constant group depth)
        const int tn = (t + 1 < TT) ? t + 1 : t;
        if (j < 16) cp_async16(&xs[bufx ^ 1][cb][cc * 4], gsrc + tn * II);
        cp_commit();
        cp_wait1();          // current step's x resident
        __syncwarp();        // h + x visible warp-wide

        ull ai[BPW], af[BPW], ag[BPW], ao[BPW];
        #pragma unroll
        for (int bb = 0; bb < BPW; bb++) {
            ai[bb] = biasp[0]; af[bb] = biasp[1];
            ag[bb] = biasp[2]; ao[bb] = biasp[3];
        }

        // ---- load x pairs (broadcast LDS.128) ----
        ull xp[BPW][8];
        #pragma unroll
        for (int bb = 0; bb < BPW; bb++) {
            const ulonglong2* xs2 = reinterpret_cast<const ulonglong2*>(&xs[bufx][bb][0]);
            ulonglong2 q0 = xs2[0], q1 = xs2[1], q2 = xs2[2], q3 = xs2[3];
            xp[bb][0] = q0.x; xp[bb][1] = q0.y; xp[bb][2] = q1.x; xp[bb][3] = q1.y;
            xp[bb][4] = q2.x; xp[bb][5] = q2.y; xp[bb][6] = q3.x; xp[bb][7] = q3.y;
        }

        // ---- input projection: one weight read feeds 4 batches ----
        #pragma unroll
        for (int i2 = 0; i2 < 8; i2++) {
            ulonglong2 a  = wA[i2 * 32];
            ulonglong2 w2 = wB[i2 * 32];
            #pragma unroll
            for (int bb = 0; bb < BPW; bb++) {
                ffma2(ai[bb], a.x,  xp[bb][i2]);
                ffma2(af[bb], a.y,  xp[bb][i2]);
                ffma2(ag[bb], w2.x, xp[bb][i2]);
                ffma2(ao[bb], w2.y, xp[bb][i2]);
            }
        }

        // ---- recurrent matvec: register weights, 16 independent chains ----
        #pragma unroll
        for (int kk = 0; kk < 8; kk++) {
            ulonglong2 hq[BPW];
            #pragma unroll
            for (int bb = 0; bb < BPW; bb++)
                hq[bb] = reinterpret_cast<const ulonglong2*>(&h_s[bufx][bb][0])[kk];
            #pragma unroll
            for (int bb = 0; bb < BPW; bb++) {
                ffma2(ai[bb], whh2[0][2*kk], hq[bb].x); ffma2(ai[bb], whh2[0][2*kk+1], hq[bb].y);
                ffma2(af[bb], whh2[1][2*kk], hq[bb].x); ffma2(af[bb], whh2[1][2*kk+1], hq[bb].y);
                ffma2(ag[bb], whh2[2][2*kk], hq[bb].x); ffma2(ag[bb], whh2[2][2*kk+1], hq[bb].y);
                ffma2(ao[bb], whh2[3][2*kk], hq[bb].x); ffma2(ao[bb], whh2[3][2*kk+1], hq[bb].y);
            }
        }

        // ---- activations (MUFU.TANH; i,f,o pre-scaled by 0.5) ----
        #pragma unroll
        for (int bb = 0; bb < BPW; bb++) {
            float gi = fmaf(tanh_a(hadd2(ai[bb])), 0.5f, 0.5f);
            float gf = fmaf(tanh_a(hadd2(af[bb])), 0.5f, 0.5f);
            float gg = tanh_a(hadd2(ag[bb]));
            float go = fmaf(tanh_a(hadd2(ao[bb])), 0.5f, 0.5f);
            c[bb] = fmaf(gf, c[bb], gi * gg);
            h[bb] = go * tanh_a(c[bb]);
        }
    }

    // ---- final FC (O=1): 4 warp reductions ----
    float wf = W_fc[j];
    float v[BPW];
    #pragma unroll
    for (int bb = 0; bb < BPW; bb++) v[bb] = h[bb] * wf;
    #pragma unroll
    for (int off = 16; off; off >>= 1) {
        #pragma unroll
        for (int bb = 0; bb < BPW; bb++)
            v[bb] += __shfl_xor_sync(0xffffffffu, v[bb], off);
    }
    if (j == 0) {
        float bf = b_fc[0];
        #pragma unroll
        for (int bb = 0; bb < BPW; bb++)
            out[b0 + bb] = v[bb] + bf;
    }
}

extern "C" void kernel_launch(void* const* d_in, const int* in_sizes, int n_in,
                              void* d_out, int out_size) {
    (void)in_sizes; (void)n_in; (void)out_size;
    const float* x    = (const float*)d_in[0];
    const float* W_ih = (const float*)d_in[1];
    const float* W_hh = (const float*)d_in[2];
    const float* b_ih = (const float*)d_in[3];
    const float* b_hh = (const float*)d_in[4];
    const float* W_fc = (const float*)d_in[5];
    const float* b_fc = (const float*)d_in[6];
    float* out = (float*)d_out;

    dim3 grid(BB / BPW);   // 1024 one-warp blocks -> ~7 warps/SM, balanced
    dim3 block(32);
    lstm_warp4_kernel<<<grid, block>>>(x, W_ih, W_hh, b_ih, b_hh, W_fc, b_fc, out);
}

// round 7
// speedup vs baseline: 1.0572x; 1.0572x over previous
#include <cuda_runtime.h>

// SimpleLSTM: B=4096, T=256, I=16, H=32, O=1 (fp32)
// R5 config (128 CTAs x 256 thr, warp = 4 batches, W_hh f32x2 pairs in regs)
// + software-pipelined step boundary: x-projection of step t+1 is issued in
// the latency shadow of step t's activation (MUFU) chain. x rides a 4-slot
// cp.async ring with prefetch distance 2; one syncwarp per step.

#define BB 4096
#define TT 256
#define II 16
#define HH 32
#define WARPS_PER_BLK 8
#define THREADS (WARPS_PER_BLK * 32)
#define BPW 4   // batches per warp

typedef unsigned long long ull;

__device__ __forceinline__ void ffma2(ull& acc, ull a, ull b) {
    asm("fma.rn.f32x2 %0, %1, %2, %0;" : "+l"(acc) : "l"(a), "l"(b));
}
__device__ __forceinline__ float hadd2(ull v) {
    float lo, hi;
    asm("mov.b64 {%0, %1}, %2;" : "=f"(lo), "=f"(hi) : "l"(v));
    return lo + hi;
}
__device__ __forceinline__ ull pack2(float lo, float hi) {
    ull r;
    asm("mov.b64 %0, {%1, %2};" : "=l"(r) : "f"(lo), "f"(hi));
    return r;
}
__device__ __forceinline__ float tanh_a(float v) {
    float r;
    asm("tanh.approx.f32 %0, %1;" : "=f"(r) : "f"(v));   // MUFU.TANH
    return r;
}
__device__ __forceinline__ void cp_async16(void* smem_dst, const void* gsrc) {
    unsigned saddr = (unsigned)__cvta_generic_to_shared(smem_dst);
    asm volatile("cp.async.ca.shared.global [%0], [%1], 16;" :: "r"(saddr), "l"(gsrc));
}
__device__ __forceinline__ void cp_commit() {
    asm volatile("cp.async.commit_group;" ::: "memory");
}
__device__ __forceinline__ void cp_wait1() {
    asm volatile("cp.async.wait_group 1;" ::: "memory");
}

__global__ void __launch_bounds__(THREADS, 1)
lstm_pipe_kernel(const float* __restrict__ x,      // [B,T,I]
                 const float* __restrict__ W_ih,   // [4H,I]
                 const float* __restrict__ W_hh,   // [4H,H]
                 const float* __restrict__ b_ih,   // [4H]
                 const float* __restrict__ b_hh,   // [4H]
                 const float* __restrict__ W_fc,   // [1,H]
                 const float* __restrict__ b_fc,   // [1]
                 float* __restrict__ out)          // [B,1]
{
    // wihA[i2][j] = {0.5*Wi pair, 0.5*Wf pair}; wihB[i2][j] = {Wg pair, 0.5*Wo pair}
    __shared__ float4 wihA[II / 2][HH];
    __shared__ float4 wihB[II / 2][HH];
    __shared__ float  h_s[WARPS_PER_BLK][2][BPW][HH];   // h broadcast, dbl-buffered
    __shared__ float  xs[WARPS_PER_BLK][4][BPW][II];    // x ring, 4 slots

    const int tid = threadIdx.x;
    const int wid = tid >> 5;
    const int j   = tid & 31;
    const int b0  = (blockIdx.x * WARPS_PER_BLK + wid) * BPW;

    const float gsc[4] = {0.5f, 0.5f, 1.0f, 0.5f};   // sigmoid fold for i,f,o

    // ---- stage W_ih (once per block), pre-scaled ----
    for (int idx = tid; idx < (II / 2) * HH; idx += THREADS) {
        int i2 = idx >> 5, jj = idx & 31;
        wihA[i2][jj] = make_float4(0.5f * W_ih[(0 * HH + jj) * II + 2 * i2],
                                   0.5f * W_ih[(0 * HH + jj) * II + 2 * i2 + 1],
                                   0.5f * W_ih[(1 * HH + jj) * II + 2 * i2],
                                   0.5f * W_ih[(1 * HH + jj) * II + 2 * i2 + 1]);
        wihB[i2][jj] = make_float4(W_ih[(2 * HH + jj) * II + 2 * i2],
                                   W_ih[(2 * HH + jj) * II + 2 * i2 + 1],
                                   0.5f * W_ih[(3 * HH + jj) * II + 2 * i2],
                                   0.5f * W_ih[(3 * HH + jj) * II + 2 * i2 + 1]);
    }
    __syncthreads();

    // ---- W_hh rows (4 gates) as packed pairs, pre-scaled (128 regs) ----
    ull whh2[4][HH / 2];
    #pragma unroll
    for (int g = 0; g < 4; g++) {
        const float* wrow = W_hh + (g * HH + j) * HH;
        #pragma unroll
        for (int k2 = 0; k2 < HH / 2; k2++)
            whh2[g][k2] = pack2(gsc[g] * wrow[2 * k2], gsc[g] * wrow[2 * k2 + 1]);
    }

    ull biasp[4];
    #pragma unroll
    for (int g = 0; g < 4; g++)
        biasp[g] = pack2(gsc[g] * (b_ih[g * HH + j] + b_hh[g * HH + j]), 0.0f);

    const ulonglong2* wA = reinterpret_cast<const ulonglong2*>(&wihA[0][j]);
    const ulonglong2* wB = reinterpret_cast<const ulonglong2*>(&wihB[0][j]);

    // cp.async lane mapping: lanes 0..15 -> batch j>>2, 16B chunk j&3
    const int cb = j >> 2, cc = j & 3;
    const float* gsrc = x + (long)(b0 + cb) * TT * II + cc * 4;

    float h[BPW] = {0.f, 0.f, 0.f, 0.f};
    float c[BPW] = {0.f, 0.f, 0.f, 0.f};

    // h[-1] = 0 lives in buffer 1 (iter 0 reads (0-1)&1 = 1)
    #pragma unroll
    for (int bb = 0; bb < BPW; bb++)
        h_s[wid][1][bb][j] = 0.0f;

    // prefetch x0, x1 (distance-2 ring)
    if (j < 16) cp_async16(&xs[wid][0][cb][cc * 4], gsrc);
    cp_commit();
    if (j < 16) cp_async16(&xs[wid][1][cb][cc * 4], gsrc + II);
    cp_commit();
    cp_wait1();      // x0 resident
    __syncwarp();

    // ---- prologue: acc(0) = bias + x-proj(x0) ----
    ull ai[BPW], af[BPW], ag[BPW], ao[BPW];
    #pragma unroll
    for (int bb = 0; bb < BPW; bb++) {
        ai[bb] = biasp[0]; af[bb] = biasp[1];
        ag[bb] = biasp[2]; ao[bb] = biasp[3];
    }
    #pragma unroll
    for (int i2 = 0; i2 < 8; i2++) {
        ulonglong2 a  = wA[i2 * 32];
        ulonglong2 w2 = wB[i2 * 32];
        #pragma unroll
        for (int bb = 0; bb < BPW; bb++) {
            ull xp = reinterpret_cast<const ull*>(&xs[wid][0][bb][0])[i2];
            ffma2(ai[bb], a.x,  xp);
            ffma2(af[bb], a.y,  xp);
            ffma2(ag[bb], w2.x, xp);
            ffma2(ao[bb], w2.y, xp);
        }
    }

    #pragma unroll 1
    for (int t = 0; t < TT; t++) {
        const int hprev = (t & 1) ^ 1;     // holds h[t-1]
        const int hcur  = t & 1;

        // ---- recurrent matvec(t): acc += W_hh * h[t-1] (register weights) ----
        #pragma unroll
        for (int kk = 0; kk < 8; kk++) {
            ulonglong2 hq[BPW];
            #pragma unroll
            for (int bb = 0; bb < BPW; bb++)
                hq[bb] = reinterpret_cast<const ulonglong2*>(&h_s[wid][hprev][bb][0])[kk];
            #pragma unroll
            for (int bb = 0; bb < BPW; bb++) {
                ffma2(ai[bb], whh2[0][2*kk], hq[bb].x); ffma2(ai[bb], whh2[0][2*kk+1], hq[bb].y);
                ffma2(af[bb], whh2[1][2*kk], hq[bb].x); ffma2(af[bb], whh2[1][2*kk+1], hq[bb].y);
                ffma2(ag[bb], whh2[2][2*kk], hq[bb].x); ffma2(ag[bb], whh2[2][2*kk+1], hq[bb].y);
                ffma2(ao[bb], whh2[3][2*kk], hq[bb].x); ffma2(ao[bb], whh2[3][2*kk+1], hq[bb].y);
            }
        }

        // ---- activations(t): issue MUFU chains (results consumed late) ----
        float gi[BPW], gf[BPW], gg[BPW], go[BPW];
        #pragma unroll
        for (int bb = 0; bb < BPW; bb++) {
            gi[bb] = tanh_a(hadd2(ai[bb]));
            gf[bb] = tanh_a(hadd2(af[bb]));
            gg[bb] = tanh_a(hadd2(ag[bb]));
            go[bb] = tanh_a(hadd2(ao[bb]));
        }

        // ---- x ring: issue cp for x[t+2], ensure x[t+1] resident ----
        const int t2 = (t + 2 < TT) ? t + 2 : TT - 1;
        if (j < 16) cp_async16(&xs[wid][(t + 2) & 3][cb][cc * 4], gsrc + (long)t2 * II);
        cp_commit();
        cp_wait1();

        // ---- x-proj(t+1) into fresh accumulators (independent of h[t];
        //      fills the MUFU latency shadow) ----
        ull ni[BPW], nf[BPW], ng[BPW], no[BPW];
        #pragma unroll
        for (int bb = 0; bb < BPW; bb++) {
            ni[bb] = biasp[0]; nf[bb] = biasp[1];
            ng[bb] = biasp[2]; no[bb] = biasp[3];
        }
        const int xbuf = (t + 1) & 3;
        #pragma unroll
        for (int i2 = 0; i2 < 8; i2++) {
            ulonglong2 a  = wA[i2 * 32];
            ulonglong2 w2 = wB[i2 * 32];
            #pragma unroll
            for (int bb = 0; bb < BPW; bb++) {
                ull xp = reinterpret_cast<const ull*>(&xs[wid][xbuf][bb][0])[i2];
                ffma2(ni[bb], a.x,  xp);
                ffma2(nf[bb], a.y,  xp);
                ffma2(ng[bb], w2.x, xp);
                ffma2(no[bb], w2.y, xp);
            }
        }

        // ---- finalize state(t), store h[t], one syncwarp ----
        #pragma unroll
        for (int bb = 0; bb < BPW; bb++) {
            float fi = fmaf(gi[bb], 0.5f, 0.5f);
            float ff = fmaf(gf[bb], 0.5f, 0.5f);
            float fo = fmaf(go[bb], 0.5f, 0.5f);
            c[bb] = fmaf(ff, c[bb], fi * gg[bb]);
            h[bb] = fo * tanh_a(c[bb]);
            h_s[wid][hcur][bb][j] = h[bb];
        }
        __syncwarp();

        // rotate accumulators
        #pragma unroll
        for (int bb = 0; bb < BPW; bb++) {
            ai[bb] = ni[bb]; af[bb] = nf[bb];
            ag[bb] = ng[bb]; ao[bb] = no[bb];
        }
    }

    // ---- final FC (O=1): 4 warp reductions ----
    float wf = W_fc[j];
    float v[BPW];
    #pragma unroll
    for (int bb = 0; bb < BPW; bb++) v[bb] = h[bb] * wf;
    #pragma unroll
    for (int off = 16; off; off >>= 1) {
        #pragma unroll
        for (int bb = 0; bb < BPW; bb++)
            v[bb] += __shfl_xor_sync(0xffffffffu, v[bb], off);
    }
    if (j == 0) {
        float bf = b_fc[0];
        #pragma unroll
        for (int bb = 0; bb < BPW; bb++)
            out[b0 + bb] = v[bb] + bf;
    }
}

extern "C" void kernel_launch(void* const* d_in, const int* in_sizes, int n_in,
                              void* d_out, int out_size) {
    (void)in_sizes; (void)n_in; (void)out_size;
    const float* x    = (const float*)d_in[0];
    const float* W_ih = (const float*)d_in[1];
    const float* W_hh = (const float*)d_in[2];
    const float* b_ih = (const float*)d_in[3];
    const float* b_hh = (const float*)d_in[4];
    const float* W_fc = (const float*)d_in[5];
    const float* b_fc = (const float*)d_in[6];
    float* out = (float*)d_out;

    dim3 grid(BB / (BPW * WARPS_PER_BLK));   // 128 blocks (R5 config)
    dim3 block(THREADS);
    lstm_pipe_kernel<<<grid, block>>>(x, W_ih, W_hh, b_ih, b_hh, W_fc, b_fc, out);
}